// round 6
// baseline (speedup 1.0000x reference)
#include <cuda_runtime.h>
#include <math.h>

#define N_USER  100000
#define N_ITEM  100000
#define N_NODES 200000
#define NNZ     6400000
#define EMB     64
#define BATCH   1024
#define NSLOTS  (3*BATCH)
#define ROWS_PER_WARP 4
#define WARPS_PER_BLK 8
#define ROWS_PER_BLK  (ROWS_PER_WARP*WARPS_PER_BLK)
#define N_TILES       (N_NODES / ROWS_PER_BLK)   // 6250
#define LAYER_GRID    592                        // ~4 blocks/SM on 148 SMs

// ---------------- scratch (device globals: allocation-free) ----------------
__device__ float g_ego1[(size_t)N_NODES * EMB];
__device__ float g_ego2[(size_t)N_NODES * EMB];
__device__ int   g_rowptr[N_NODES + 1];

// ---------------- packed f32x2 helpers (Blackwell FFMA2) ----------------
__device__ __forceinline__ unsigned long long pack2(float x, float y) {
    unsigned long long r;
    asm("mov.b64 %0, {%1, %2};" : "=l"(r) : "f"(x), "f"(y));
    return r;
}
__device__ __forceinline__ void unpack2(unsigned long long v, float& x, float& y) {
    asm("mov.b64 {%0, %1}, %2;" : "=f"(x), "=f"(y) : "l"(v));
}
__device__ __forceinline__ unsigned long long fma2(unsigned long long a,
                                                   unsigned long long b,
                                                   unsigned long long c) {
    unsigned long long d;
    asm("fma.rn.f32x2 %0, %1, %2, %3;" : "=l"(d) : "l"(a), "l"(b), "l"(c));
    return d;
}

// ---------------- build CSR rowptr from sorted adj_row ----------------
__global__ void build_rowptr_kernel(const int* __restrict__ row) {
    int i = blockIdx.x * blockDim.x + threadIdx.x;
    if (i > NNZ) return;
    int cur  = (i < NNZ) ? __ldg(row + i)     : N_NODES;
    int prev = (i > 0)   ? __ldg(row + i - 1) : -1;
    for (int r = prev + 1; r <= cur; ++r) g_rowptr[r] = i;
}

// ---------------- row pointer select: layer 1 reads ue/ie directly ----------------
template<bool FIRST>
__device__ __forceinline__ const float* row_base(const float* __restrict__ g,
                                                 const float* __restrict__ ue,
                                                 const float* __restrict__ ie,
                                                 int c)
{
    if (FIRST)
        return (c < N_USER) ? (ue + (size_t)c * EMB)
                            : (ie + (size_t)(c - N_USER) * EMB);
    return g + (size_t)c * EMB;
}

// ---------------- warp SpMM accumulate: 4 independent chains for MLP ----------------
template<bool FIRST>
__device__ __forceinline__ float2 spmm_row(const float* __restrict__ g,
                                           const float* __restrict__ ue,
                                           const float* __restrict__ ie,
                                           const int*   __restrict__ col,
                                           const float* __restrict__ val,
                                           int e0, int e1, int lane)
{
    float2 a0 = make_float2(0.f, 0.f);
    float2 a1 = make_float2(0.f, 0.f);
    float2 a2 = make_float2(0.f, 0.f);
    float2 a3 = make_float2(0.f, 0.f);

    for (int base = e0; base < e1; base += 32) {
        int e = base + lane;
        int c = 0; float v = 0.f;
        if (e < e1) { c = __ldg(col + e); v = __ldg(val + e); }
        int n = min(32, e1 - base);

        if (n == 32) {
            #pragma unroll
            for (int j = 0; j < 8; ++j) {
                int   c0 = __shfl_sync(0xffffffffu, c, j);
                int   c1 = __shfl_sync(0xffffffffu, c, j + 8);
                int   c2 = __shfl_sync(0xffffffffu, c, j + 16);
                int   c3 = __shfl_sync(0xffffffffu, c, j + 24);
                float v0 = __shfl_sync(0xffffffffu, v, j);
                float v1 = __shfl_sync(0xffffffffu, v, j + 8);
                float v2 = __shfl_sync(0xffffffffu, v, j + 16);
                float v3 = __shfl_sync(0xffffffffu, v, j + 24);
                float2 x0 = __ldg((const float2*)row_base<FIRST>(g, ue, ie, c0) + lane);
                float2 x1 = __ldg((const float2*)row_base<FIRST>(g, ue, ie, c1) + lane);
                float2 x2 = __ldg((const float2*)row_base<FIRST>(g, ue, ie, c2) + lane);
                float2 x3 = __ldg((const float2*)row_base<FIRST>(g, ue, ie, c3) + lane);
                a0.x = fmaf(v0, x0.x, a0.x); a0.y = fmaf(v0, x0.y, a0.y);
                a1.x = fmaf(v1, x1.x, a1.x); a1.y = fmaf(v1, x1.y, a1.y);
                a2.x = fmaf(v2, x2.x, a2.x); a2.y = fmaf(v2, x2.y, a2.y);
                a3.x = fmaf(v3, x3.x, a3.x); a3.y = fmaf(v3, x3.y, a3.y);
            }
        } else {
            #pragma unroll 4
            for (int j = 0; j < n; ++j) {
                int   cj = __shfl_sync(0xffffffffu, c, j);
                float vj = __shfl_sync(0xffffffffu, v, j);
                float2 x = __ldg((const float2*)row_base<FIRST>(g, ue, ie, cj) + lane);
                a0.x = fmaf(vj, x.x, a0.x);
                a0.y = fmaf(vj, x.y, a0.y);
            }
        }
    }
    a0.x += a1.x + a2.x + a3.x;   // fp32 reassociation noise ~1e-7 << 1e-3
    a0.y += a1.y + a2.y + a3.y;
    return a0;
}

// ---------------- fused layer: persistent blocks, 4 rows per warp ----------------
// Weights loaded to shared ONCE per block; block grid-strides over row tiles.
template<bool FIRST>
__global__ __launch_bounds__(256) void layer_kernel(
    const float* __restrict__ ego_in,   // unused when FIRST
    float*       __restrict__ ego_out,
    const float* __restrict__ ue,
    const float* __restrict__ ie,
    const int*   __restrict__ col,
    const float* __restrict__ val,
    const float* __restrict__ Wgc, const float* __restrict__ bgc,
    const float* __restrict__ Wbi, const float* __restrict__ bbi)
{
    __shared__ float  sWgc[EMB * EMB];                        // 16 KB
    __shared__ float  sWbi[EMB * EMB];                        // 16 KB
    __shared__ float2 sST[WARPS_PER_BLK][ROWS_PER_WARP][EMB]; // 16 KB {S[k],T[k]}

    {   // cooperative weight load, once per block
        int t = threadIdx.x;
        const float4* wg4 = (const float4*)Wgc;
        const float4* wb4 = (const float4*)Wbi;
        float4* sg4 = (float4*)sWgc;
        float4* sb4 = (float4*)sWbi;
        #pragma unroll
        for (int k = 0; k < 4; ++k) {
            sg4[t + 256 * k] = wg4[t + 256 * k];
            sb4[t + 256 * k] = wb4[t + 256 * k];
        }
    }
    __syncthreads();

    const int w    = threadIdx.x >> 5;
    const int lane = threadIdx.x & 31;

    // bias packed once (registers)
    unsigned long long b2;
    {
        float bx = __ldg(bgc + 2 * lane)     + __ldg(bbi + 2 * lane);
        float by = __ldg(bgc + 2 * lane + 1) + __ldg(bbi + 2 * lane + 1);
        b2 = pack2(bx, by);
    }

    for (int tile = blockIdx.x; tile < N_TILES; tile += gridDim.x) {
        const int r0 = (tile * WARPS_PER_BLK + w) * ROWS_PER_WARP;

        // ---- SpMM for 4 rows; store interleaved {S,T} ----
        #pragma unroll
        for (int i = 0; i < ROWS_PER_WARP; ++i) {
            const int r  = r0 + i;
            const int e0 = __ldg(&g_rowptr[r]);
            const int e1 = __ldg(&g_rowptr[r + 1]);
            float2 acc = spmm_row<FIRST>(ego_in, ue, ie, col, val, e0, e1, lane);
            float2 eg  = *(const float2*)(row_base<FIRST>(ego_in, ue, ie, r) + 2 * lane);
            sST[w][i][2 * lane]     = make_float2(acc.x, acc.x * eg.x);
            sST[w][i][2 * lane + 1] = make_float2(acc.y, acc.y * eg.y);
        }
        __syncwarp();

        // ---- dense: f_i = leaky( S_i @ Wgc + T_i @ Wbi + b ) ----
        unsigned long long f[ROWS_PER_WARP];
        #pragma unroll
        for (int i = 0; i < ROWS_PER_WARP; ++i) f[i] = b2;

        #pragma unroll 4
        for (int k = 0; k < EMB; ++k) {
            unsigned long long wg = *(const unsigned long long*)&sWgc[k * EMB + 2 * lane];
            unsigned long long wb = *(const unsigned long long*)&sWbi[k * EMB + 2 * lane];
            #pragma unroll
            for (int i = 0; i < ROWS_PER_WARP; ++i) {
                float2 st = sST[w][i][k];              // broadcast LDS.64
                f[i] = fma2(pack2(st.x, st.x), wg, f[i]);
                f[i] = fma2(pack2(st.y, st.y), wb, f[i]);
            }
        }
        __syncwarp();   // dense reads done before next tile overwrites sST

        #pragma unroll
        for (int i = 0; i < ROWS_PER_WARP; ++i) {
            float x, y;
            unpack2(f[i], x, y);
            x = x > 0.f ? x : 0.2f * x;
            y = y > 0.f ? y : 0.2f * y;
            *(float2*)(ego_out + (size_t)(r0 + i) * EMB + 2 * lane) = make_float2(x, y);
        }
    }
}

// ---------------- final: layer-3 only at selected rows + gather + l2norms ----------------
__global__ __launch_bounds__(256) void final_kernel(
    const int*   __restrict__ users,
    const int*   __restrict__ pos,
    const int*   __restrict__ neg,
    const float* __restrict__ ue,
    const float* __restrict__ ie,
    const int*   __restrict__ col,
    const float* __restrict__ val,
    const float* __restrict__ Wgc, const float* __restrict__ bgc,
    const float* __restrict__ Wbi, const float* __restrict__ bbi,
    float* __restrict__ out)
{
    __shared__ float  sWgc[EMB * EMB];
    __shared__ float  sWbi[EMB * EMB];
    __shared__ float2 sST[8][EMB];

    {
        int t = threadIdx.x;
        const float4* wg4 = (const float4*)Wgc;
        const float4* wb4 = (const float4*)Wbi;
        float4* sg4 = (float4*)sWgc;
        float4* sb4 = (float4*)sWbi;
        #pragma unroll
        for (int k = 0; k < 4; ++k) {
            sg4[t + 256 * k] = wg4[t + 256 * k];
            sb4[t + 256 * k] = wb4[t + 256 * k];
        }
    }
    __syncthreads();

    const int w    = threadIdx.x >> 5;
    const int lane = threadIdx.x & 31;
    const int slot = blockIdx.x * 8 + w;
    if (slot >= NSLOTS) return;

    int node;
    if (slot < BATCH)            node = __ldg(users + slot);
    else if (slot < 2 * BATCH)   node = N_USER + __ldg(pos + slot - BATCH);
    else                         node = N_USER + __ldg(neg + slot - 2 * BATCH);

    float* o = out + (size_t)slot * (4 * EMB);

    // part 0: raw ego0 (directly from input embeddings)
    {
        const float* p = (node < N_USER) ? (ue + (size_t)node * EMB)
                                         : (ie + (size_t)(node - N_USER) * EMB);
        float2 v = __ldg((const float2*)p + lane);
        *(float2*)(o + 2 * lane) = v;
    }

    // part 1: l2norm(ego1[node])
    {
        float2 v = *(const float2*)(g_ego1 + (size_t)node * EMB + 2 * lane);
        float s = v.x * v.x + v.y * v.y;
        #pragma unroll
        for (int off = 16; off; off >>= 1) s += __shfl_xor_sync(0xffffffffu, s, off);
        float inv = 1.f / fmaxf(sqrtf(s), 1e-12f);
        *(float2*)(o + EMB + 2 * lane) = make_float2(v.x * inv, v.y * inv);
    }

    // part 2: l2norm(ego2[node])
    float2 eg2 = *(const float2*)(g_ego2 + (size_t)node * EMB + 2 * lane);
    {
        float s = eg2.x * eg2.x + eg2.y * eg2.y;
        #pragma unroll
        for (int off = 16; off; off >>= 1) s += __shfl_xor_sync(0xffffffffu, s, off);
        float inv = 1.f / fmaxf(sqrtf(s), 1e-12f);
        *(float2*)(o + 2 * EMB + 2 * lane) = make_float2(eg2.x * inv, eg2.y * inv);
    }

    // part 3: sparse layer-3 for this row only, then l2norm
    {
        const int e0 = __ldg(&g_rowptr[node]);
        const int e1 = __ldg(&g_rowptr[node + 1]);
        float2 acc = spmm_row<false>(g_ego2, ue, ie, col, val, e0, e1, lane);

        sST[w][2 * lane]     = make_float2(acc.x, acc.x * eg2.x);
        sST[w][2 * lane + 1] = make_float2(acc.y, acc.y * eg2.y);
        __syncwarp();

        float fx = __ldg(bgc + 2 * lane)     + __ldg(bbi + 2 * lane);
        float fy = __ldg(bgc + 2 * lane + 1) + __ldg(bbi + 2 * lane + 1);
        unsigned long long f = pack2(fx, fy);
        #pragma unroll 8
        for (int k = 0; k < EMB; ++k) {
            unsigned long long wg = *(const unsigned long long*)&sWgc[k * EMB + 2 * lane];
            unsigned long long wb = *(const unsigned long long*)&sWbi[k * EMB + 2 * lane];
            float2 st = sST[w][k];
            f = fma2(pack2(st.x, st.x), wg, f);
            f = fma2(pack2(st.y, st.y), wb, f);
        }
        float x, y;
        unpack2(f, x, y);
        x = x > 0.f ? x : 0.2f * x;
        y = y > 0.f ? y : 0.2f * y;

        float s = x * x + y * y;
        #pragma unroll
        for (int off = 16; off; off >>= 1) s += __shfl_xor_sync(0xffffffffu, s, off);
        float inv = 1.f / fmaxf(sqrtf(s), 1e-12f);
        *(float2*)(o + 3 * EMB + 2 * lane) = make_float2(x * inv, y * inv);
    }
}

// ---------------- launch ----------------
extern "C" void kernel_launch(void* const* d_in, const int* in_sizes, int n_in,
                              void* d_out, int out_size)
{
    const int*   users    = (const int*)  d_in[0];
    const int*   pos      = (const int*)  d_in[1];
    const int*   neg      = (const int*)  d_in[2];
    const int*   adj_row  = (const int*)  d_in[3];
    const int*   adj_col  = (const int*)  d_in[4];
    const float* adj_val  = (const float*)d_in[5];
    const float* user_emb = (const float*)d_in[6];
    const float* item_emb = (const float*)d_in[7];
    const float* W_gc_0   = (const float*)d_in[8];
    const float* b_gc_0   = (const float*)d_in[9];
    const float* W_bi_0   = (const float*)d_in[10];
    const float* b_bi_0   = (const float*)d_in[11];
    const float* W_gc_1   = (const float*)d_in[12];
    const float* b_gc_1   = (const float*)d_in[13];
    const float* W_bi_1   = (const float*)d_in[14];
    const float* b_bi_1   = (const float*)d_in[15];
    const float* W_gc_2   = (const float*)d_in[16];
    const float* b_gc_2   = (const float*)d_in[17];
    const float* W_bi_2   = (const float*)d_in[18];
    const float* b_bi_2   = (const float*)d_in[19];
    float* out = (float*)d_out;

    float* ego1;
    float* ego2;
    cudaGetSymbolAddress((void**)&ego1, g_ego1);
    cudaGetSymbolAddress((void**)&ego2, g_ego2);

    build_rowptr_kernel<<<(NNZ + 1 + 255) / 256, 256>>>(adj_row);
    layer_kernel<true><<<LAYER_GRID, 256>>>(nullptr, ego1, user_emb, item_emb,
                                            adj_col, adj_val,
                                            W_gc_0, b_gc_0, W_bi_0, b_bi_0);
    layer_kernel<false><<<LAYER_GRID, 256>>>(ego1, ego2, user_emb, item_emb,
                                             adj_col, adj_val,
                                             W_gc_1, b_gc_1, W_bi_1, b_bi_1);
    final_kernel<<<NSLOTS / 8, 256>>>(users, pos, neg, user_emb, item_emb,
                                      adj_col, adj_val,
                                      W_gc_2, b_gc_2, W_bi_2, b_bi_2,
                                      out);
}

// round 15
// speedup vs baseline: 2.0076x; 2.0076x over previous
#include <cuda_runtime.h>
#include <math.h>

#define N_USER  100000
#define N_ITEM  100000
#define N_NODES 200000
#define NNZ     6400000
#define EMB     64
#define BATCH   1024
#define NSLOTS  (3*BATCH)
#define ROWS_PER_WARP 4
#define WARPS_PER_BLK 8
#define ROWS_PER_BLK  (ROWS_PER_WARP*WARPS_PER_BLK)
#define N_TILES       (N_NODES / ROWS_PER_BLK)   // 6250
#define LAYER_GRID    592                        // 4 blocks/SM on 148 SMs

typedef unsigned long long ull;

// ---------------- scratch (device globals: allocation-free) ----------------
__device__ float g_ego1[(size_t)N_NODES * EMB];
__device__ float g_ego2[(size_t)N_NODES * EMB];
__device__ int   g_rowptr[N_NODES + 1];

// ---------------- packed f32x2 helpers (Blackwell FFMA2/FADD2) ----------------
__device__ __forceinline__ ull pack2(float x, float y) {
    ull r; asm("mov.b64 %0, {%1, %2};" : "=l"(r) : "f"(x), "f"(y)); return r;
}
__device__ __forceinline__ void unpack2(ull v, float& x, float& y) {
    asm("mov.b64 {%0, %1}, %2;" : "=f"(x), "=f"(y) : "l"(v));
}
__device__ __forceinline__ ull fma2(ull a, ull b, ull c) {
    ull d; asm("fma.rn.f32x2 %0, %1, %2, %3;" : "=l"(d) : "l"(a), "l"(b), "l"(c)); return d;
}
__device__ __forceinline__ ull add2(ull a, ull b) {
    ull d; asm("add.rn.f32x2 %0, %1, %2;" : "=l"(d) : "l"(a), "l"(b)); return d;
}

// ---------------- build CSR rowptr from sorted adj_row ----------------
__global__ void build_rowptr_kernel(const int* __restrict__ row) {
    int i = blockIdx.x * blockDim.x + threadIdx.x;
    if (i > NNZ) return;
    int cur  = (i < NNZ) ? __ldg(row + i)     : N_NODES;
    int prev = (i > 0)   ? __ldg(row + i - 1) : -1;
    for (int r = prev + 1; r <= cur; ++r) g_rowptr[r] = i;
}

// ---------------- row pointer select: layer 1 reads ue/ie directly ----------------
template<bool FIRST>
__device__ __forceinline__ const float* row_base(const float* __restrict__ g,
                                                 const float* __restrict__ ue,
                                                 const float* __restrict__ ie,
                                                 int c)
{
    if (FIRST)
        return (c < N_USER) ? (ue + (size_t)c * EMB)
                            : (ie + (size_t)(c - N_USER) * EMB);
    return g + (size_t)c * EMB;
}

// ---------------- warp SpMM: uniform int4/float4 edge loads, no shfl ----------------
template<bool FIRST>
__device__ __forceinline__ float2 spmm_row(const float* __restrict__ g,
                                           const float* __restrict__ ue,
                                           const float* __restrict__ ie,
                                           const int*   __restrict__ col,
                                           const float* __restrict__ val,
                                           int e0, int e1, int lane)
{
    ull a0 = 0ull, a1 = 0ull, a2 = 0ull, a3 = 0ull;  // bit pattern {0f,0f}
    int e = e0;

    // head: align e to 4 (col/val base is 256B-aligned by cudaMalloc)
    int nhead = (4 - (e0 & 3)) & 3;
    if (nhead > e1 - e0) nhead = e1 - e0;
    for (int t = 0; t < nhead; ++t, ++e) {
        int   c = __ldg(col + e);
        float v = __ldg(val + e);
        float2 x = __ldg((const float2*)row_base<FIRST>(g, ue, ie, c) + lane);
        a0 = fma2(pack2(v, v), pack2(x.x, x.y), a0);
    }

    // main: groups of 4 edges via uniform vector loads (L1 broadcast);
    // unroll 4 -> up to 16 gather loads in flight per warp
    #pragma unroll 4
    for (; e + 4 <= e1; e += 4) {
        int4   c4 = __ldg((const int4*)  (col + e));
        float4 v4 = __ldg((const float4*)(val + e));
        float2 x0 = __ldg((const float2*)row_base<FIRST>(g, ue, ie, c4.x) + lane);
        float2 x1 = __ldg((const float2*)row_base<FIRST>(g, ue, ie, c4.y) + lane);
        float2 x2 = __ldg((const float2*)row_base<FIRST>(g, ue, ie, c4.z) + lane);
        float2 x3 = __ldg((const float2*)row_base<FIRST>(g, ue, ie, c4.w) + lane);
        a0 = fma2(pack2(v4.x, v4.x), pack2(x0.x, x0.y), a0);
        a1 = fma2(pack2(v4.y, v4.y), pack2(x1.x, x1.y), a1);
        a2 = fma2(pack2(v4.z, v4.z), pack2(x2.x, x2.y), a2);
        a3 = fma2(pack2(v4.w, v4.w), pack2(x3.x, x3.y), a3);
    }

    // tail
    for (; e < e1; ++e) {
        int   c = __ldg(col + e);
        float v = __ldg(val + e);
        float2 x = __ldg((const float2*)row_base<FIRST>(g, ue, ie, c) + lane);
        a0 = fma2(pack2(v, v), pack2(x.x, x.y), a0);
    }

    a0 = add2(a0, a1);
    a2 = add2(a2, a3);
    a0 = add2(a0, a2);        // fp32 reassociation noise ~1e-7 << 1e-3
    float rx, ry; unpack2(a0, rx, ry);
    return make_float2(rx, ry);
}

// ---------------- fused layer: persistent blocks, 4 rows per warp ----------------
template<bool FIRST>
__global__ __launch_bounds__(256, 4) void layer_kernel(
    const float* __restrict__ ego_in,   // unused when FIRST
    float*       __restrict__ ego_out,
    const float* __restrict__ ue,
    const float* __restrict__ ie,
    const int*   __restrict__ col,
    const float* __restrict__ val,
    const float* __restrict__ Wgc, const float* __restrict__ bgc,
    const float* __restrict__ Wbi, const float* __restrict__ bbi)
{
    // interleaved weights: sW[k][l] = {Wgc[k][2l], Wgc[k][2l+1], Wbi[k][2l], Wbi[k][2l+1]}
    __shared__ float4 sW[EMB][EMB / 2];                       // 32 KB
    __shared__ float2 sST[WARPS_PER_BLK][ROWS_PER_WARP][EMB]; // 16 KB {S[k],T[k]}

    for (int idx = threadIdx.x; idx < EMB * (EMB / 2); idx += 256) {
        int k = idx >> 5;          // / 32
        int l = idx & 31;
        float2 wg = __ldg((const float2*)(Wgc + k * EMB) + l);
        float2 wb = __ldg((const float2*)(Wbi + k * EMB) + l);
        sW[k][l] = make_float4(wg.x, wg.y, wb.x, wb.y);
    }
    __syncthreads();

    const int w    = threadIdx.x >> 5;
    const int lane = threadIdx.x & 31;

    ull b2;
    {
        float bx = __ldg(bgc + 2 * lane)     + __ldg(bbi + 2 * lane);
        float by = __ldg(bgc + 2 * lane + 1) + __ldg(bbi + 2 * lane + 1);
        b2 = pack2(bx, by);
    }

    #pragma unroll 1
    for (int tile = blockIdx.x; tile < N_TILES; tile += gridDim.x) {
        const int r0 = (tile * WARPS_PER_BLK + w) * ROWS_PER_WARP;

        // rowptr for all 4 rows hoisted (5 uniform loads per quad)
        int rp[ROWS_PER_WARP + 1];
        #pragma unroll
        for (int i = 0; i <= ROWS_PER_WARP; ++i) rp[i] = __ldg(&g_rowptr[r0 + i]);

        // ---- SpMM for 4 rows; one STS.128 per row ----
        #pragma unroll
        for (int i = 0; i < ROWS_PER_WARP; ++i) {
            const int r = r0 + i;
            float2 acc = spmm_row<FIRST>(ego_in, ue, ie, col, val, rp[i], rp[i + 1], lane);
            float2 eg  = *(const float2*)(row_base<FIRST>(ego_in, ue, ie, r) + 2 * lane);
            *(float4*)&sST[w][i][2 * lane] =
                make_float4(acc.x, acc.x * eg.x, acc.y, acc.y * eg.y);
        }
        __syncwarp();

        // ---- dense: f_i = leaky( S_i @ Wgc + T_i @ Wbi + b ), 2 k's per LDS ----
        ull f[ROWS_PER_WARP];
        #pragma unroll
        for (int i = 0; i < ROWS_PER_WARP; ++i) f[i] = b2;

        #pragma unroll 4
        for (int kk = 0; kk < EMB / 2; ++kk) {
            float4 wA = sW[2 * kk][lane];
            float4 wB = sW[2 * kk + 1][lane];
            ull wgA = pack2(wA.x, wA.y), wbA = pack2(wA.z, wA.w);
            ull wgB = pack2(wB.x, wB.y), wbB = pack2(wB.z, wB.w);
            #pragma unroll
            for (int i = 0; i < ROWS_PER_WARP; ++i) {
                float4 st = *(const float4*)&sST[w][i][2 * kk];  // {s_k,t_k,s_k+1,t_k+1}
                f[i] = fma2(pack2(st.x, st.x), wgA, f[i]);
                f[i] = fma2(pack2(st.y, st.y), wbA, f[i]);
                f[i] = fma2(pack2(st.z, st.z), wgB, f[i]);
                f[i] = fma2(pack2(st.w, st.w), wbB, f[i]);
            }
        }
        __syncwarp();   // dense reads done before next tile overwrites sST

        #pragma unroll
        for (int i = 0; i < ROWS_PER_WARP; ++i) {
            float x, y;
            unpack2(f[i], x, y);
            x = x > 0.f ? x : 0.2f * x;
            y = y > 0.f ? y : 0.2f * y;
            *(float2*)(ego_out + (size_t)(r0 + i) * EMB + 2 * lane) = make_float2(x, y);
        }
    }
}

// ---------------- final: layer-3 at selected rows + gather + l2norms ----------------
// 128 threads / 4 warps per block; weights via __ldg (L1-resident), no weight smem.
__global__ __launch_bounds__(128) void final_kernel(
    const int*   __restrict__ users,
    const int*   __restrict__ pos,
    const int*   __restrict__ neg,
    const float* __restrict__ ue,
    const float* __restrict__ ie,
    const int*   __restrict__ col,
    const float* __restrict__ val,
    const float* __restrict__ Wgc, const float* __restrict__ bgc,
    const float* __restrict__ Wbi, const float* __restrict__ bbi,
    float* __restrict__ out)
{
    __shared__ float2 sST[4][EMB];   // 2 KB

    const int w    = threadIdx.x >> 5;
    const int lane = threadIdx.x & 31;
    const int slot = blockIdx.x * 4 + w;
    if (slot >= NSLOTS) return;

    int node;
    if (slot < BATCH)            node = __ldg(users + slot);
    else if (slot < 2 * BATCH)   node = N_USER + __ldg(pos + slot - BATCH);
    else                         node = N_USER + __ldg(neg + slot - 2 * BATCH);

    float* o = out + (size_t)slot * (4 * EMB);

    // part 0: raw ego0 (directly from input embeddings)
    {
        const float* p = (node < N_USER) ? (ue + (size_t)node * EMB)
                                         : (ie + (size_t)(node - N_USER) * EMB);
        float2 v = __ldg((const float2*)p + lane);
        *(float2*)(o + 2 * lane) = v;
    }

    // part 1: l2norm(ego1[node])
    {
        float2 v = *(const float2*)(g_ego1 + (size_t)node * EMB + 2 * lane);
        float s = v.x * v.x + v.y * v.y;
        #pragma unroll
        for (int off = 16; off; off >>= 1) s += __shfl_xor_sync(0xffffffffu, s, off);
        float inv = 1.f / fmaxf(sqrtf(s), 1e-12f);
        *(float2*)(o + EMB + 2 * lane) = make_float2(v.x * inv, v.y * inv);
    }

    // part 2: l2norm(ego2[node])
    float2 eg2 = *(const float2*)(g_ego2 + (size_t)node * EMB + 2 * lane);
    {
        float s = eg2.x * eg2.x + eg2.y * eg2.y;
        #pragma unroll
        for (int off = 16; off; off >>= 1) s += __shfl_xor_sync(0xffffffffu, s, off);
        float inv = 1.f / fmaxf(sqrtf(s), 1e-12f);
        *(float2*)(o + 2 * EMB + 2 * lane) = make_float2(eg2.x * inv, eg2.y * inv);
    }

    // part 3: sparse layer-3 for this row only, then l2norm
    {
        const int e0 = __ldg(&g_rowptr[node]);
        const int e1 = __ldg(&g_rowptr[node + 1]);
        float2 acc = spmm_row<false>(g_ego2, ue, ie, col, val, e0, e1, lane);

        *(float4*)&sST[w][2 * lane] =
            make_float4(acc.x, acc.x * eg2.x, acc.y, acc.y * eg2.y);
        __syncwarp();

        float fx = __ldg(bgc + 2 * lane)     + __ldg(bbi + 2 * lane);
        float fy = __ldg(bgc + 2 * lane + 1) + __ldg(bbi + 2 * lane + 1);
        ull f = pack2(fx, fy);

        #pragma unroll 4
        for (int kk = 0; kk < EMB / 2; ++kk) {
            float4 st = *(const float4*)&sST[w][2 * kk];
            float2 wgA = __ldg((const float2*)(Wgc + (2 * kk)     * EMB) + lane);
            float2 wbA = __ldg((const float2*)(Wbi + (2 * kk)     * EMB) + lane);
            float2 wgB = __ldg((const float2*)(Wgc + (2 * kk + 1) * EMB) + lane);
            float2 wbB = __ldg((const float2*)(Wbi + (2 * kk + 1) * EMB) + lane);
            f = fma2(pack2(st.x, st.x), pack2(wgA.x, wgA.y), f);
            f = fma2(pack2(st.y, st.y), pack2(wbA.x, wbA.y), f);
            f = fma2(pack2(st.z, st.z), pack2(wgB.x, wgB.y), f);
            f = fma2(pack2(st.w, st.w), pack2(wbB.x, wbB.y), f);
        }
        float x, y;
        unpack2(f, x, y);
        x = x > 0.f ? x : 0.2f * x;
        y = y > 0.f ? y : 0.2f * y;

        float s = x * x + y * y;
        #pragma unroll
        for (int off = 16; off; off >>= 1) s += __shfl_xor_sync(0xffffffffu, s, off);
        float inv = 1.f / fmaxf(sqrtf(s), 1e-12f);
        *(float2*)(o + 3 * EMB + 2 * lane) = make_float2(x * inv, y * inv);
    }
}

// ---------------- launch ----------------
extern "C" void kernel_launch(void* const* d_in, const int* in_sizes, int n_in,
                              void* d_out, int out_size)
{
    const int*   users    = (const int*)  d_in[0];
    const int*   pos      = (const int*)  d_in[1];
    const int*   neg      = (const int*)  d_in[2];
    const int*   adj_row  = (const int*)  d_in[3];
    const int*   adj_col  = (const int*)  d_in[4];
    const float* adj_val  = (const float*)d_in[5];
    const float* user_emb = (const float*)d_in[6];
    const float* item_emb = (const float*)d_in[7];
    const float* W_gc_0   = (const float*)d_in[8];
    const float* b_gc_0   = (const float*)d_in[9];
    const float* W_bi_0   = (const float*)d_in[10];
    const float* b_bi_0   = (const float*)d_in[11];
    const float* W_gc_1   = (const float*)d_in[12];
    const float* b_gc_1   = (const float*)d_in[13];
    const float* W_bi_1   = (const float*)d_in[14];
    const float* b_bi_1   = (const float*)d_in[15];
    const float* W_gc_2   = (const float*)d_in[16];
    const float* b_gc_2   = (const float*)d_in[17];
    const float* W_bi_2   = (const float*)d_in[18];
    const float* b_bi_2   = (const float*)d_in[19];
    float* out = (float*)d_out;

    float* ego1;
    float* ego2;
    cudaGetSymbolAddress((void**)&ego1, g_ego1);
    cudaGetSymbolAddress((void**)&ego2, g_ego2);

    build_rowptr_kernel<<<(NNZ + 1 + 255) / 256, 256>>>(adj_row);
    layer_kernel<true><<<LAYER_GRID, 256>>>(nullptr, ego1, user_emb, item_emb,
                                            adj_col, adj_val,
                                            W_gc_0, b_gc_0, W_bi_0, b_bi_0);
    layer_kernel<false><<<LAYER_GRID, 256>>>(ego1, ego2, user_emb, item_emb,
                                             adj_col, adj_val,
                                             W_gc_1, b_gc_1, W_bi_1, b_bi_1);
    final_kernel<<<NSLOTS / 4, 128>>>(users, pos, neg, user_emb, item_emb,
                                      adj_col, adj_val,
                                      W_gc_2, b_gc_2, W_bi_2, b_bi_2,
                                      out);
}